// round 3
// baseline (speedup 1.0000x reference)
#include <cuda_runtime.h>
#include <cuda_bf16.h>
#include <cstdint>

// Problem dims (fixed)
#define BB   32
#define NN   2048
#define FF   1024
#define HSZ  8192   // 4*N
#define HFZ  4096   // 4*F
#define OUTF 1024

// ---------------- scratch (device globals; no allocations allowed) ----------
__device__ float g_b1[(size_t)BB * FF * NN];   // 67,108,864 floats (256 MB)
__device__ float g_b2[(size_t)BB * FF * NN];   // 256 MB
__device__ int   g_b3[(size_t)BB * FF * NN];   // p (argsort), 256 MB
__device__ float g_h [(size_t)BB * FF * HSZ];  // 268,435,456 floats (1 GB); reused for h2

// ---------------- f32x2 packed-FMA helpers ----------------------------------
__device__ __forceinline__ unsigned long long pack2(float x) {
    unsigned long long d;
    unsigned int r = __float_as_uint(x);
    asm("mov.b64 %0, {%1, %1};" : "=l"(d) : "r"(r));
    return d;
}
__device__ __forceinline__ unsigned long long ffma2(unsigned long long a,
                                                    unsigned long long b,
                                                    unsigned long long c) {
    unsigned long long d;
    asm("fma.rn.f32x2 %0, %1, %2, %3;" : "=l"(d) : "l"(a), "l"(b), "l"(c));
    return d;
}
__device__ __forceinline__ float unpack_lo(unsigned long long v) {
    return __uint_as_float((unsigned int)(v & 0xffffffffull));
}
__device__ __forceinline__ float unpack_hi(unsigned long long v) {
    return __uint_as_float((unsigned int)(v >> 32));
}

// ---------------- batched transpose: in [batch, R, C] -> out [batch, C, R] --
__global__ void transpose_batched(const float* __restrict__ in,
                                  float* __restrict__ out, int R, int C) {
    __shared__ float tile[32][33];
    int b  = blockIdx.z;
    int c0 = blockIdx.x * 32;
    int r0 = blockIdx.y * 32;
    const float* ib = in  + (size_t)b * R * C;
    float*       ob = out + (size_t)b * R * C;
    int x = threadIdx.x;
    #pragma unroll
    for (int i = threadIdx.y; i < 32; i += 8)
        tile[i][x] = ib[(size_t)(r0 + i) * C + (c0 + x)];
    __syncthreads();
    #pragma unroll
    for (int i = threadIdx.y; i < 32; i += 8)
        ob[(size_t)(c0 + i) * R + (r0 + x)] = tile[x][i];
}

// ---------------- per-row stable argsort (bitonic on 64-bit keys) -----------
// xm row length 2048. Outputs: p (argsort indices) and xs[j] = xm[inv[j]].
__global__ __launch_bounds__(1024) void sort_rows(const float* __restrict__ xm,
                                                  float* __restrict__ xs,
                                                  int* __restrict__ p) {
    const int n = NN;
    __shared__ unsigned long long keys[NN];
    __shared__ float vals[NN];
    __shared__ int   inv[NN];
    size_t row = (size_t)blockIdx.x * n;
    int tid = threadIdx.x;

    for (int i = tid; i < n; i += 1024) {
        float v = xm[row + i];
        vals[i] = v;
        unsigned int u = __float_as_uint(v);
        u = (u & 0x80000000u) ? ~u : (u | 0x80000000u);   // monotone map
        keys[i] = ((unsigned long long)u << 32) | (unsigned int)i; // stable tie-break
    }
    __syncthreads();

    for (int k = 2; k <= n; k <<= 1) {
        for (int j = k >> 1; j > 0; j >>= 1) {
            #pragma unroll 2
            for (int i = tid; i < n; i += 1024) {
                int ixj = i ^ j;
                if (ixj > i) {
                    bool up = ((i & k) == 0);
                    unsigned long long a = keys[i];
                    unsigned long long b = keys[ixj];
                    if ((a > b) == up) { keys[i] = b; keys[ixj] = a; }
                }
            }
            __syncthreads();
        }
    }

    for (int i = tid; i < n; i += 1024) {
        int pi = (int)(keys[i] & 0xffffffffull);
        p[row + i] = pi;
        inv[pi] = i;               // inv = argsort(p) = p^{-1}
    }
    __syncthreads();
    for (int i = tid; i < n; i += 1024)
        xs[row + i] = vals[inv[i]];   // take_along_axis(xm, inv)
}

// ---------------- per-row unsort: out[j] = ys[p[j]] --------------------------
__global__ void unsort_rows(const float* __restrict__ ys,
                            const int* __restrict__ p,
                            float* __restrict__ out) {
    const int n = NN;
    __shared__ float buf[NN];
    size_t row = (size_t)blockIdx.x * n;
    for (int i = threadIdx.x; i < n; i += blockDim.x) buf[i] = ys[row + i];
    __syncthreads();
    for (int i = threadIdx.x; i < n; i += blockDim.x)
        out[row + i] = buf[p[row + i]];
}

// ---------------- NT GEMM: C[m,n] = act( sum_k A[m,k]*B[n,k] + bias[n] (+ skip[m,n]) )
// A [M,K] rm, B [N,K] rm, C [M,N] rm. M%128==0, N%128==0, K%8==0.
// 128x128 block, 256 threads, 8x8 micro-tile, f32x2 packed FMA, double-buffered smem.
template<bool RELU, bool SKIP>
__global__ __launch_bounds__(256, 2)
void gemm_nt(const float* __restrict__ A, const float* __restrict__ Bm,
             const float* __restrict__ bias, const float* __restrict__ skip,
             float* __restrict__ C, int M, int N, int K) {
    constexpr int BK = 8;
    constexpr int LDS = 132;                  // padded to kill bank conflicts
    __shared__ __align__(16) float As[2][BK][LDS];
    __shared__ __align__(16) float Bs[2][BK][LDS];

    int tid = threadIdx.x;
    int bm = blockIdx.y * 128;
    int bn = blockIdx.x * 128;
    int ty = tid >> 4;          // 0..15
    int tx = tid & 15;          // 0..15

    int lr = tid >> 1;          // 0..127 (tile row for loading)
    int lc = (tid & 1) * 4;     // 0 or 4

    const float* Ag = A  + (size_t)(bm + lr) * K + lc;
    const float* Bg = Bm + (size_t)(bn + lr) * K + lc;

    unsigned long long acc[8][4];
    #pragma unroll
    for (int i = 0; i < 8; i++)
        #pragma unroll
        for (int j = 0; j < 4; j++) acc[i][j] = 0ull;

    // prefetch first tile
    float4 ra = *(const float4*)Ag;
    float4 rb = *(const float4*)Bg;
    As[0][lc + 0][lr] = ra.x; As[0][lc + 1][lr] = ra.y;
    As[0][lc + 2][lr] = ra.z; As[0][lc + 3][lr] = ra.w;
    Bs[0][lc + 0][lr] = rb.x; Bs[0][lc + 1][lr] = rb.y;
    Bs[0][lc + 2][lr] = rb.z; Bs[0][lc + 3][lr] = rb.w;
    __syncthreads();

    int nk = K / BK;
    int buf = 0;
    for (int kt = 0; kt < nk; ++kt) {
        if (kt + 1 < nk) {
            ra = *(const float4*)(Ag + (size_t)(kt + 1) * BK);
            rb = *(const float4*)(Bg + (size_t)(kt + 1) * BK);
        }
        #pragma unroll
        for (int k = 0; k < BK; k++) {
            float4 a0 = *(const float4*)&As[buf][k][ty * 8];
            float4 a1 = *(const float4*)&As[buf][k][ty * 8 + 4];
            ulonglong2 b0 = *(const ulonglong2*)&Bs[buf][k][tx * 8];
            ulonglong2 b1 = *(const ulonglong2*)&Bs[buf][k][tx * 8 + 4];
            float av[8] = {a0.x, a0.y, a0.z, a0.w, a1.x, a1.y, a1.z, a1.w};
            unsigned long long bv[4] = {b0.x, b0.y, b1.x, b1.y};
            #pragma unroll
            for (int i = 0; i < 8; i++) {
                unsigned long long a2 = pack2(av[i]);
                #pragma unroll
                for (int j = 0; j < 4; j++)
                    acc[i][j] = ffma2(a2, bv[j], acc[i][j]);
            }
        }
        if (kt + 1 < nk) {
            buf ^= 1;
            As[buf][lc + 0][lr] = ra.x; As[buf][lc + 1][lr] = ra.y;
            As[buf][lc + 2][lr] = ra.z; As[buf][lc + 3][lr] = ra.w;
            Bs[buf][lc + 0][lr] = rb.x; Bs[buf][lc + 1][lr] = rb.y;
            Bs[buf][lc + 2][lr] = rb.z; Bs[buf][lc + 3][lr] = rb.w;
            __syncthreads();
        }
    }

    // epilogue
    float bias8[8];
    *(float4*)&bias8[0] = *(const float4*)&bias[bn + tx * 8];
    *(float4*)&bias8[4] = *(const float4*)&bias[bn + tx * 8 + 4];

    #pragma unroll
    for (int i = 0; i < 8; i++) {
        size_t off = (size_t)(bm + ty * 8 + i) * N + bn + tx * 8;
        float o[8];
        #pragma unroll
        for (int j = 0; j < 4; j++) {
            o[2 * j]     = unpack_lo(acc[i][j]) + bias8[2 * j];
            o[2 * j + 1] = unpack_hi(acc[i][j]) + bias8[2 * j + 1];
        }
        if (SKIP) {
            float4 s0 = *(const float4*)&skip[off];
            float4 s1 = *(const float4*)&skip[off + 4];
            o[0] += s0.x; o[1] += s0.y; o[2] += s0.z; o[3] += s0.w;
            o[4] += s1.x; o[5] += s1.y; o[6] += s1.z; o[7] += s1.w;
        }
        if (RELU) {
            #pragma unroll
            for (int j = 0; j < 8; j++) o[j] = fmaxf(o[j], 0.0f);
        }
        *(float4*)&C[off]     = make_float4(o[0], o[1], o[2], o[3]);
        *(float4*)&C[off + 4] = make_float4(o[4], o[5], o[6], o[7]);
    }
}

// ---------------- launch ------------------------------------------------------
extern "C" void kernel_launch(void* const* d_in, const int* in_sizes, int n_in,
                              void* d_out, int out_size) {
    const float* x   = (const float*)d_in[0];
    const float* sw1 = (const float*)d_in[1];
    const float* sb1 = (const float*)d_in[2];
    const float* sw2 = (const float*)d_in[3];
    const float* sb2 = (const float*)d_in[4];
    const float* fw1 = (const float*)d_in[5];
    const float* fb1 = (const float*)d_in[6];
    const float* fw2 = (const float*)d_in[7];
    const float* fb2 = (const float*)d_in[8];
    float* out = (float*)d_out;

    void *p1, *p2, *p3, *ph;
    cudaGetSymbolAddress(&p1, g_b1);
    cudaGetSymbolAddress(&p2, g_b2);
    cudaGetSymbolAddress(&p3, g_b3);
    cudaGetSymbolAddress(&ph, g_h);
    float* b1 = (float*)p1;
    float* b2 = (float*)p2;
    int*   bp = (int*)p3;
    float* bh = (float*)ph;

    const int M1 = BB * FF;   // 32768
    const int M2 = BB * NN;   // 65536

    // 1) xm = transpose(x): [B,N,F] -> [B,F,N]
    transpose_batched<<<dim3(FF / 32, NN / 32, BB), dim3(32, 8)>>>(x, b1, NN, FF);

    // 2) stable argsort rows of xm -> xs (b2), p (bp)
    sort_rows<<<M1, 1024>>>(b1, b2, bp);

    // 3) h = relu(xs @ sw1^T + sb1): [32768,2048] x [8192,2048] -> bh
    gemm_nt<true, false><<<dim3(HSZ / 128, M1 / 128), 256>>>(
        b2, sw1, sb1, nullptr, bh, M1, HSZ, NN);

    // 4) y_sorted = h @ sw2^T + sb2 + xs: [32768,8192] x [2048,8192] -> b1
    gemm_nt<false, true><<<dim3(NN / 128, M1 / 128), 256>>>(
        bh, sw2, sb2, b2, b1, M1, NN, HSZ);

    // 5) unsort: yfin[j] = y_sorted[p[j]] -> b2   (still [B,F,N])
    unsort_rows<<<M1, 256>>>(b1, bp, b2);

    // 6) transpose back: [B,F,N] -> [B,N,F] -> b1
    transpose_batched<<<dim3(NN / 32, FF / 32, BB), dim3(32, 8)>>>(b2, b1, FF, NN);

    // 7) h2 = relu(y @ fw1^T + fb1): [65536,1024] x [4096,1024] -> bh
    gemm_nt<true, false><<<dim3(HFZ / 128, M2 / 128), 256>>>(
        b1, fw1, fb1, nullptr, bh, M2, HFZ, FF);

    // 8) out = h2 @ fw2^T + fb2: [65536,4096] x [1024,4096] -> d_out
    gemm_nt<false, false><<<dim3(OUTF / 128, M2 / 128), 256>>>(
        bh, fw2, fb2, nullptr, out, M2, OUTF, HFZ);

    (void)in_sizes; (void)n_in; (void)out_size;
}

// round 7
// speedup vs baseline: 2.4198x; 2.4198x over previous
#include <cuda_runtime.h>
#include <cuda_bf16.h>
#include <cstdint>

// Problem dims (fixed)
#define BB   32
#define NN   2048
#define FF   1024
#define HSZ  8192   // 4*N
#define HFZ  4096   // 4*F
#define OUTF 1024

// ---------------- scratch (device globals; no allocations allowed) ----------
__device__ float g_f1[(size_t)BB * FF * NN];            // 256 MB
__device__ float g_f2[(size_t)BB * FF * NN];            // 256 MB
__device__ int   g_p [(size_t)BB * FF * NN];            // 256 MB
__device__ __nv_bfloat16 g_xh[(size_t)BB * FF * NN];    // xs / y planes
__device__ __nv_bfloat16 g_xl[(size_t)BB * FF * NN];
__device__ __nv_bfloat16 g_hh[(size_t)BB * FF * HSZ];   // h / h2 planes
__device__ __nv_bfloat16 g_hl[(size_t)BB * FF * HSZ];
__device__ __nv_bfloat16 g_w1h[(size_t)HSZ * NN],  g_w1l[(size_t)HSZ * NN];
__device__ __nv_bfloat16 g_w2h[(size_t)NN * HSZ],  g_w2l[(size_t)NN * HSZ];
__device__ __nv_bfloat16 g_w3h[(size_t)HFZ * FF],  g_w3l[(size_t)HFZ * FF];
__device__ __nv_bfloat16 g_w4h[(size_t)OUTF * HFZ], g_w4l[(size_t)OUTF * HFZ];

// ======================= PTX helpers (compute_103-safe) ======================
__device__ __forceinline__ uint32_t smem_u32(const void* p) {
    uint32_t a;
    asm("{ .reg .u64 t; cvta.to.shared.u64 t, %1; cvt.u32.u64 %0, t; }"
        : "=r"(a) : "l"(p));
    return a;
}
__device__ __forceinline__ void cp_async16(uint32_t dst, const void* src) {
    asm volatile("cp.async.cg.shared.global [%0], [%1], 16;" :: "r"(dst), "l"(src));
}
__device__ __forceinline__ void cp_commit() {
    asm volatile("cp.async.commit_group;" ::: "memory");
}
__device__ __forceinline__ void cp_wait2() {
    asm volatile("cp.async.wait_group 2;" ::: "memory");
}
__device__ __forceinline__ void ldsm_x4(uint32_t* r, uint32_t addr) {
    asm volatile("ldmatrix.sync.aligned.m8n8.x4.shared.b16 {%0,%1,%2,%3}, [%4];"
                 : "=r"(r[0]), "=r"(r[1]), "=r"(r[2]), "=r"(r[3]) : "r"(addr));
}
__device__ __forceinline__ void mma_bf16(float* d, const uint32_t* a,
                                         uint32_t b0, uint32_t b1) {
    asm volatile(
        "mma.sync.aligned.m16n8k16.row.col.f32.bf16.bf16.f32 "
        "{%0,%1,%2,%3}, {%4,%5,%6,%7}, {%8,%9}, {%0,%1,%2,%3};"
        : "+f"(d[0]), "+f"(d[1]), "+f"(d[2]), "+f"(d[3])
        : "r"(a[0]), "r"(a[1]), "r"(a[2]), "r"(a[3]), "r"(b0), "r"(b1));
}
__device__ __forceinline__ uint32_t swz128(uint32_t off) {
    return off ^ ((off >> 3) & 0x70u);
}

// ---------------- batched transpose: in [batch, R, C] -> out [batch, C, R] --
__global__ void transpose_batched(const float* __restrict__ in,
                                  float* __restrict__ out, int R, int C) {
    __shared__ float tile[32][33];
    int b  = blockIdx.z;
    int c0 = blockIdx.x * 32;
    int r0 = blockIdx.y * 32;
    const float* ib = in  + (size_t)b * R * C;
    float*       ob = out + (size_t)b * R * C;
    int x = threadIdx.x;
    #pragma unroll
    for (int i = threadIdx.y; i < 32; i += 8)
        tile[i][x] = ib[(size_t)(r0 + i) * C + (c0 + x)];
    __syncthreads();
    #pragma unroll
    for (int i = threadIdx.y; i < 32; i += 8)
        ob[(size_t)(c0 + i) * R + (r0 + x)] = tile[x][i];
}

// transpose + bf16 hi/lo split output
__global__ void transpose_split(const float* __restrict__ in,
                                __nv_bfloat16* __restrict__ oh,
                                __nv_bfloat16* __restrict__ ol, int R, int C) {
    __shared__ float tile[32][33];
    int b  = blockIdx.z;
    int c0 = blockIdx.x * 32;
    int r0 = blockIdx.y * 32;
    const float* ib = in + (size_t)b * R * C;
    size_t ob = (size_t)b * R * C;
    int x = threadIdx.x;
    #pragma unroll
    for (int i = threadIdx.y; i < 32; i += 8)
        tile[i][x] = ib[(size_t)(r0 + i) * C + (c0 + x)];
    __syncthreads();
    #pragma unroll
    for (int i = threadIdx.y; i < 32; i += 8) {
        float v = tile[x][i];
        __nv_bfloat16 h = __float2bfloat16(v);
        size_t idx = ob + (size_t)(c0 + i) * R + (r0 + x);
        oh[idx] = h;
        ol[idx] = __float2bfloat16(v - __bfloat162float(h));
    }
}

// weight split: hi = bf16(w), lo = bf16(w - hi)
__global__ void split_plane(const float* __restrict__ w,
                            __nv_bfloat16* __restrict__ hi,
                            __nv_bfloat16* __restrict__ lo, size_t n) {
    size_t i = (size_t)blockIdx.x * blockDim.x + threadIdx.x;
    if (i < n) {
        float v = w[i];
        __nv_bfloat16 h = __float2bfloat16(v);
        hi[i] = h;
        lo[i] = __float2bfloat16(v - __bfloat162float(h));
    }
}

// ---------------- per-row stable argsort (bitonic on 64-bit keys) -----------
__global__ __launch_bounds__(1024) void sort_rows(const float* __restrict__ xm,
                                                  float* __restrict__ xs,
                                                  __nv_bfloat16* __restrict__ xsh,
                                                  __nv_bfloat16* __restrict__ xsl,
                                                  int* __restrict__ p) {
    const int n = NN;
    __shared__ unsigned long long keys[NN];
    __shared__ float vals[NN];
    __shared__ int   inv[NN];
    size_t row = (size_t)blockIdx.x * n;
    int tid = threadIdx.x;

    for (int i = tid; i < n; i += 1024) {
        float v = xm[row + i];
        vals[i] = v;
        unsigned int u = __float_as_uint(v);
        u = (u & 0x80000000u) ? ~u : (u | 0x80000000u);
        keys[i] = ((unsigned long long)u << 32) | (unsigned int)i;
    }
    __syncthreads();
    for (int k = 2; k <= n; k <<= 1) {
        for (int j = k >> 1; j > 0; j >>= 1) {
            #pragma unroll 2
            for (int i = tid; i < n; i += 1024) {
                int ixj = i ^ j;
                if (ixj > i) {
                    bool up = ((i & k) == 0);
                    unsigned long long a = keys[i];
                    unsigned long long b = keys[ixj];
                    if ((a > b) == up) { keys[i] = b; keys[ixj] = a; }
                }
            }
            __syncthreads();
        }
    }
    for (int i = tid; i < n; i += 1024) {
        int pi = (int)(keys[i] & 0xffffffffull);
        p[row + i] = pi;
        inv[pi] = i;
    }
    __syncthreads();
    for (int i = tid; i < n; i += 1024) {
        float v = vals[inv[i]];
        xs[row + i] = v;
        __nv_bfloat16 h = __float2bfloat16(v);
        xsh[row + i] = h;
        xsl[row + i] = __float2bfloat16(v - __bfloat162float(h));
    }
}

// ---------------- per-row unsort: out[j] = ys[p[j]] --------------------------
__global__ void unsort_rows(const float* __restrict__ ys,
                            const int* __restrict__ p,
                            float* __restrict__ out) {
    const int n = NN;
    __shared__ float buf[NN];
    size_t row = (size_t)blockIdx.x * n;
    for (int i = threadIdx.x; i < n; i += blockDim.x) buf[i] = ys[row + i];
    __syncthreads();
    for (int i = threadIdx.x; i < n; i += blockDim.x)
        out[row + i] = buf[p[row + i]];
}

// ======================= mma.sync bf16x3 NT GEMM =============================
// C[m,n] = act( sum_k A[m,k]*B[n,k] + bias[n] (+skip) ),  A~Ah+Al, B~Bh+Bl.
// 128x128 CTA tile, BK=64, 4 planes (Ah,Al,Bh,Bl) of 16KB in smem per stage,
// 3-stage cp.async pipeline. 8 warps: 4(m) x 2(n); warp tile 32x64.
// Per k16: A frags via ldmatrix.x4, B frags via ldmatrix.x4 (2 n-tiles each),
// 3 passes: Ah*Bh + Ah*Bl + Al*Bh into fp32 accumulators.
#define NSTAGES 3
#define GEMM_DYN_SMEM (NSTAGES * 65536 + 1024)

template<int RELU, int SKIP, int SPLITOUT>
__global__ __launch_bounds__(256, 1)
void gemm_mma(const __nv_bfloat16* __restrict__ Ah, const __nv_bfloat16* __restrict__ Al,
              const __nv_bfloat16* __restrict__ Bh, const __nv_bfloat16* __restrict__ Bl,
              const float* __restrict__ bias, const float* __restrict__ skip,
              float* __restrict__ Cf,
              __nv_bfloat16* __restrict__ Ch, __nv_bfloat16* __restrict__ Cl,
              int M, int Nn, int K) {
    extern __shared__ char dynsmem[];
    uint32_t tile0 = (smem_u32(dynsmem) + 1023u) & ~1023u;

    const int tid = threadIdx.x;
    const int wid = tid >> 5, lane = tid & 31;
    const int wm = wid & 3, wn = wid >> 2;        // 4 x 2 warp grid
    const int lm = lane & 15;
    const uint32_t hi16 = (uint32_t)(lane >> 4) << 4;
    const int bm = blockIdx.y * 128, bn = blockIdx.x * 128;

    // ---- loader mapping: 4096 16B chunks/stage, 16 per thread ----
    const __nv_bfloat16* srcs[16];
    uint32_t dsts[16];
    #pragma unroll
    for (int i = 0; i < 16; i++) {
        int c = tid + i * 256;
        int plane = c >> 10;            // 0:Ah 1:Al 2:Bh 3:Bl
        int r  = (c >> 3) & 127;
        int cc = c & 7;
        const __nv_bfloat16* bp = (plane == 0) ? Ah : (plane == 1) ? Al
                                 : (plane == 2) ? Bh : Bl;
        int row = ((plane < 2) ? bm : bn) + r;
        srcs[i] = bp + (size_t)row * K + cc * 8;
        dsts[i] = (uint32_t)plane * 16384u + swz128((uint32_t)(r * 128 + cc * 16));
    }

    float acc[2][8][4];
    #pragma unroll
    for (int a = 0; a < 2; a++)
        #pragma unroll
        for (int b = 0; b < 8; b++)
            #pragma unroll
            for (int c = 0; c < 4; c++) acc[a][b][c] = 0.0f;

    const int nk = K >> 6;

    // prologue: fill stages 0..NSTAGES-2
    #pragma unroll
    for (int s = 0; s < NSTAGES - 1; s++) {
        uint32_t sb = tile0 + (uint32_t)s * 65536u;
        #pragma unroll
        for (int i = 0; i < 16; i++)
            cp_async16(sb + dsts[i], srcs[i] + (size_t)s * 64);
        cp_commit();
    }

    // precompute per-thread fragment row offsets (within-tile, swizzled row term)
    uint32_t aRow[2], bRow[4];
    #pragma unroll
    for (int mt = 0; mt < 2; mt++) {
        int r = wm * 32 + mt * 16 + lm;
        aRow[mt] = (uint32_t)r * 128u | ((uint32_t)(r & 7) << 20);  // pack xor key hi
    }
    #pragma unroll
    for (int np = 0; np < 4; np++) {
        int r = wn * 64 + np * 16 + lm;
        bRow[np] = (uint32_t)r * 128u | ((uint32_t)(r & 7) << 20);
    }

    for (int kt = 0; kt < nk; ++kt) {
        // issue stage kt+NSTAGES-1
        if (kt + NSTAGES - 1 < nk) {
            uint32_t sb = tile0 + (uint32_t)((kt + NSTAGES - 1) % NSTAGES) * 65536u;
            #pragma unroll
            for (int i = 0; i < 16; i++)
                cp_async16(sb + dsts[i], srcs[i] + (size_t)(kt + NSTAGES - 1) * 64);
        }
        cp_commit();
        cp_wait2();              // stage kt resident
        __syncthreads();

        const uint32_t sb = tile0 + (uint32_t)(kt % NSTAGES) * 65536u;
        #pragma unroll
        for (int kb = 0; kb < 4; kb++) {
            const uint32_t cbase = (uint32_t)kb * 32u + hi16;
            uint32_t af[2][2][4];     // [plane][mt][4]
            #pragma unroll
            for (int mt = 0; mt < 2; mt++) {
                uint32_t xr = (aRow[mt] >> 20) << 4;
                uint32_t off = (aRow[mt] & 0xFFFFFu) + (cbase ^ xr);
                ldsm_x4(af[0][mt], sb + off);             // Ah
                ldsm_x4(af[1][mt], sb + 16384u + off);    // Al
            }
            uint32_t bf[2][4][4];     // [plane][np][4]
            #pragma unroll
            for (int np = 0; np < 4; np++) {
                uint32_t xr = (bRow[np] >> 20) << 4;
                uint32_t off = (bRow[np] & 0xFFFFFu) + (cbase ^ xr);
                ldsm_x4(bf[0][np], sb + 32768u + off);    // Bh
                ldsm_x4(bf[1][np], sb + 49152u + off);    // Bl
            }
            #pragma unroll
            for (int mt = 0; mt < 2; mt++)
                #pragma unroll
                for (int np = 0; np < 4; np++)
                    #pragma unroll
                    for (int sub = 0; sub < 2; sub++) {
                        int nt = np * 2 + sub;
                        // hi*hi
                        mma_bf16(acc[mt][nt], af[0][mt], bf[0][np][sub], bf[0][np][sub + 2]);
                        // hi*lo
                        mma_bf16(acc[mt][nt], af[0][mt], bf[1][np][sub], bf[1][np][sub + 2]);
                        // lo*hi
                        mma_bf16(acc[mt][nt], af[1][mt], bf[0][np][sub], bf[0][np][sub + 2]);
                    }
        }
        __syncthreads();
    }

    // ---------------- epilogue ----------------
    const int lr = lane >> 2;          // 0..7
    const int lc = (lane & 3) * 2;     // 0,2,4,6
    #pragma unroll
    for (int nt = 0; nt < 8; nt++) {
        int c = bn + wn * 64 + nt * 8 + lc;
        float b0 = bias[c], b1 = bias[c + 1];
        #pragma unroll
        for (int mt = 0; mt < 2; mt++) {
            #pragma unroll
            for (int half = 0; half < 2; half++) {
                int r = bm + wm * 32 + mt * 16 + lr + half * 8;
                float v0 = acc[mt][nt][half * 2 + 0] + b0;
                float v1 = acc[mt][nt][half * 2 + 1] + b1;
                size_t off = (size_t)r * Nn + c;
                if (SKIP) {
                    float2 sv = *(const float2*)(skip + off);
                    v0 += sv.x; v1 += sv.y;
                }
                if (RELU) { v0 = fmaxf(v0, 0.0f); v1 = fmaxf(v1, 0.0f); }
                if (SPLITOUT) {
                    __nv_bfloat16 h0 = __float2bfloat16(v0);
                    __nv_bfloat16 h1 = __float2bfloat16(v1);
                    __nv_bfloat16 l0 = __float2bfloat16(v0 - __bfloat162float(h0));
                    __nv_bfloat16 l1 = __float2bfloat16(v1 - __bfloat162float(h1));
                    *(__nv_bfloat162*)(Ch + off) = __nv_bfloat162(h0, h1);
                    *(__nv_bfloat162*)(Cl + off) = __nv_bfloat162(l0, l1);
                } else {
                    *(float2*)(Cf + off) = make_float2(v0, v1);
                }
            }
        }
    }
}

// ---------------- launch ------------------------------------------------------
extern "C" void kernel_launch(void* const* d_in, const int* in_sizes, int n_in,
                              void* d_out, int out_size) {
    const float* x   = (const float*)d_in[0];
    const float* sw1 = (const float*)d_in[1];
    const float* sb1 = (const float*)d_in[2];
    const float* sw2 = (const float*)d_in[3];
    const float* sb2 = (const float*)d_in[4];
    const float* fw1 = (const float*)d_in[5];
    const float* fb1 = (const float*)d_in[6];
    const float* fw2 = (const float*)d_in[7];
    const float* fb2 = (const float*)d_in[8];
    float* out = (float*)d_out;

    void *pf1, *pf2, *pp, *pxh, *pxl, *phh, *phl;
    void *pw1h, *pw1l, *pw2h, *pw2l, *pw3h, *pw3l, *pw4h, *pw4l;
    cudaGetSymbolAddress(&pf1, g_f1);  cudaGetSymbolAddress(&pf2, g_f2);
    cudaGetSymbolAddress(&pp,  g_p);
    cudaGetSymbolAddress(&pxh, g_xh);  cudaGetSymbolAddress(&pxl, g_xl);
    cudaGetSymbolAddress(&phh, g_hh);  cudaGetSymbolAddress(&phl, g_hl);
    cudaGetSymbolAddress(&pw1h, g_w1h); cudaGetSymbolAddress(&pw1l, g_w1l);
    cudaGetSymbolAddress(&pw2h, g_w2h); cudaGetSymbolAddress(&pw2l, g_w2l);
    cudaGetSymbolAddress(&pw3h, g_w3h); cudaGetSymbolAddress(&pw3l, g_w3l);
    cudaGetSymbolAddress(&pw4h, g_w4h); cudaGetSymbolAddress(&pw4l, g_w4l);
    float* f1 = (float*)pf1;  float* f2 = (float*)pf2;  int* pidx = (int*)pp;
    __nv_bfloat16* xh = (__nv_bfloat16*)pxh; __nv_bfloat16* xl = (__nv_bfloat16*)pxl;
    __nv_bfloat16* hh = (__nv_bfloat16*)phh; __nv_bfloat16* hl = (__nv_bfloat16*)phl;
    __nv_bfloat16* w1h = (__nv_bfloat16*)pw1h; __nv_bfloat16* w1l = (__nv_bfloat16*)pw1l;
    __nv_bfloat16* w2h = (__nv_bfloat16*)pw2h; __nv_bfloat16* w2l = (__nv_bfloat16*)pw2l;
    __nv_bfloat16* w3h = (__nv_bfloat16*)pw3h; __nv_bfloat16* w3l = (__nv_bfloat16*)pw3l;
    __nv_bfloat16* w4h = (__nv_bfloat16*)pw4h; __nv_bfloat16* w4l = (__nv_bfloat16*)pw4l;

    cudaFuncSetAttribute(gemm_mma<1, 0, 1>, cudaFuncAttributeMaxDynamicSharedMemorySize, GEMM_DYN_SMEM);
    cudaFuncSetAttribute(gemm_mma<0, 1, 0>, cudaFuncAttributeMaxDynamicSharedMemorySize, GEMM_DYN_SMEM);
    cudaFuncSetAttribute(gemm_mma<0, 0, 0>, cudaFuncAttributeMaxDynamicSharedMemorySize, GEMM_DYN_SMEM);

    const int M1 = BB * FF;   // 32768
    const int M2 = BB * NN;   // 65536

    // weight hi/lo planes (recomputed every call; deterministic)
    split_plane<<<((size_t)HSZ * NN + 255) / 256, 256>>>(sw1, w1h, w1l, (size_t)HSZ * NN);
    split_plane<<<((size_t)NN * HSZ + 255) / 256, 256>>>(sw2, w2h, w2l, (size_t)NN * HSZ);
    split_plane<<<((size_t)HFZ * FF + 255) / 256, 256>>>(fw1, w3h, w3l, (size_t)HFZ * FF);
    split_plane<<<((size_t)OUTF * HFZ + 255) / 256, 256>>>(fw2, w4h, w4l, (size_t)OUTF * HFZ);

    // 1) xm = transpose(x): [B,N,F] -> [B,F,N]  -> f1
    transpose_batched<<<dim3(FF / 32, NN / 32, BB), dim3(32, 8)>>>(x, f1, NN, FF);

    // 2) stable argsort rows: xs fp32 -> f2, planes -> xh/xl, p -> pidx
    sort_rows<<<M1, 1024>>>(f1, f2, xh, xl, pidx);

    // 3) h = relu(xs @ sw1^T + sb1): planes out -> hh/hl
    gemm_mma<1, 0, 1><<<dim3(HSZ / 128, M1 / 128), 256, GEMM_DYN_SMEM>>>(
        xh, xl, w1h, w1l, sb1, nullptr, nullptr, hh, hl, M1, HSZ, NN);

    // 4) y_s = h @ sw2^T + sb2 + xs: fp32 out -> f1
    gemm_mma<0, 1, 0><<<dim3(NN / 128, M1 / 128), 256, GEMM_DYN_SMEM>>>(
        hh, hl, w2h, w2l, sb2, f2, f1, nullptr, nullptr, M1, NN, HSZ);

    // 5) unsort -> f2
    unsort_rows<<<M1, 256>>>(f1, pidx, f2);

    // 6) transpose back [B,F,N]->[B,N,F] with split -> xh/xl
    transpose_split<<<dim3(NN / 32, FF / 32, BB), dim3(32, 8)>>>(f2, xh, xl, FF, NN);

    // 7) h2 = relu(y @ fw1^T + fb1): planes out -> hh/hl
    gemm_mma<1, 0, 1><<<dim3(HFZ / 128, M2 / 128), 256, GEMM_DYN_SMEM>>>(
        xh, xl, w3h, w3l, fb1, nullptr, nullptr, hh, hl, M2, HFZ, FF);

    // 8) out = h2 @ fw2^T + fb2: fp32 -> d_out
    gemm_mma<0, 0, 0><<<dim3(OUTF / 128, M2 / 128), 256, GEMM_DYN_SMEM>>>(
        hh, hl, w4h, w4l, fb2, nullptr, out, nullptr, nullptr, M2, OUTF, HFZ);

    (void)in_sizes; (void)n_in; (void)out_size;
}

// round 8
// speedup vs baseline: 2.4602x; 1.0167x over previous
#include <cuda_runtime.h>
#include <cuda_bf16.h>
#include <cstdint>

// Problem dims (fixed)
#define BB   32
#define NN   2048
#define FF   1024
#define HSZ  8192   // 4*N
#define HFZ  4096   // 4*F
#define OUTF 1024

// ---------------- scratch (device globals; no allocations allowed) ----------
__device__ float g_f1[(size_t)BB * FF * NN];            // 256 MB
__device__ float g_f2[(size_t)BB * FF * NN];            // 256 MB
__device__ int   g_p [(size_t)BB * FF * NN];            // 256 MB
__device__ __nv_bfloat16 g_xh[(size_t)BB * FF * NN];    // xs / y planes
__device__ __nv_bfloat16 g_xl[(size_t)BB * FF * NN];
__device__ __nv_bfloat16 g_hh[(size_t)BB * FF * HSZ];   // h / h2 planes
__device__ __nv_bfloat16 g_hl[(size_t)BB * FF * HSZ];
__device__ __nv_bfloat16 g_w1h[(size_t)HSZ * NN],  g_w1l[(size_t)HSZ * NN];
__device__ __nv_bfloat16 g_w2h[(size_t)NN * HSZ],  g_w2l[(size_t)NN * HSZ];
__device__ __nv_bfloat16 g_w3h[(size_t)HFZ * FF],  g_w3l[(size_t)HFZ * FF];
__device__ __nv_bfloat16 g_w4h[(size_t)OUTF * HFZ], g_w4l[(size_t)OUTF * HFZ];

// ======================= PTX helpers (compute_103-safe) ======================
__device__ __forceinline__ uint32_t smem_u32(const void* p) {
    uint32_t a;
    asm("{ .reg .u64 t; cvta.to.shared.u64 t, %1; cvt.u32.u64 %0, t; }"
        : "=r"(a) : "l"(p));
    return a;
}
__device__ __forceinline__ void cp_async16(uint32_t dst, const void* src) {
    asm volatile("cp.async.cg.shared.global [%0], [%1], 16;" :: "r"(dst), "l"(src));
}
__device__ __forceinline__ void cp_commit() {
    asm volatile("cp.async.commit_group;" ::: "memory");
}
__device__ __forceinline__ void cp_wait2() {
    asm volatile("cp.async.wait_group 2;" ::: "memory");
}
__device__ __forceinline__ void ldsm_x4(uint32_t* r, uint32_t addr) {
    asm volatile("ldmatrix.sync.aligned.m8n8.x4.shared.b16 {%0,%1,%2,%3}, [%4];"
                 : "=r"(r[0]), "=r"(r[1]), "=r"(r[2]), "=r"(r[3]) : "r"(addr));
}
__device__ __forceinline__ void mma_bf16(float* d, const uint32_t* a,
                                         uint32_t b0, uint32_t b1) {
    asm volatile(
        "mma.sync.aligned.m16n8k16.row.col.f32.bf16.bf16.f32 "
        "{%0,%1,%2,%3}, {%4,%5,%6,%7}, {%8,%9}, {%0,%1,%2,%3};"
        : "+f"(d[0]), "+f"(d[1]), "+f"(d[2]), "+f"(d[3])
        : "r"(a[0]), "r"(a[1]), "r"(a[2]), "r"(a[3]), "r"(b0), "r"(b1));
}
__device__ __forceinline__ uint32_t swz128(uint32_t off) {
    return off ^ ((off >> 3) & 0x70u);
}

// ---------------- batched transpose: in [batch, R, C] -> out [batch, C, R] --
__global__ void transpose_batched(const float* __restrict__ in,
                                  float* __restrict__ out, int R, int C) {
    __shared__ float tile[32][33];
    int b  = blockIdx.z;
    int c0 = blockIdx.x * 32;
    int r0 = blockIdx.y * 32;
    const float* ib = in  + (size_t)b * R * C;
    float*       ob = out + (size_t)b * R * C;
    int x = threadIdx.x;
    #pragma unroll
    for (int i = threadIdx.y; i < 32; i += 8)
        tile[i][x] = ib[(size_t)(r0 + i) * C + (c0 + x)];
    __syncthreads();
    #pragma unroll
    for (int i = threadIdx.y; i < 32; i += 8)
        ob[(size_t)(c0 + i) * R + (r0 + x)] = tile[x][i];
}

// transpose + bf16 hi/lo split output
__global__ void transpose_split(const float* __restrict__ in,
                                __nv_bfloat16* __restrict__ oh,
                                __nv_bfloat16* __restrict__ ol, int R, int C) {
    __shared__ float tile[32][33];
    int b  = blockIdx.z;
    int c0 = blockIdx.x * 32;
    int r0 = blockIdx.y * 32;
    const float* ib = in + (size_t)b * R * C;
    size_t ob = (size_t)b * R * C;
    int x = threadIdx.x;
    #pragma unroll
    for (int i = threadIdx.y; i < 32; i += 8)
        tile[i][x] = ib[(size_t)(r0 + i) * C + (c0 + x)];
    __syncthreads();
    #pragma unroll
    for (int i = threadIdx.y; i < 32; i += 8) {
        float v = tile[x][i];
        __nv_bfloat16 h = __float2bfloat16(v);
        size_t idx = ob + (size_t)(c0 + i) * R + (r0 + x);
        oh[idx] = h;
        ol[idx] = __float2bfloat16(v - __bfloat162float(h));
    }
}

// weight split: hi = bf16(w), lo = bf16(w - hi)
__global__ void split_plane(const float* __restrict__ w,
                            __nv_bfloat16* __restrict__ hi,
                            __nv_bfloat16* __restrict__ lo, size_t n) {
    size_t i = (size_t)blockIdx.x * blockDim.x + threadIdx.x;
    if (i < n) {
        float v = w[i];
        __nv_bfloat16 h = __float2bfloat16(v);
        hi[i] = h;
        lo[i] = __float2bfloat16(v - __bfloat162float(h));
    }
}

// ---------------- per-row stable argsort (bitonic on 64-bit keys) -----------
__global__ __launch_bounds__(1024) void sort_rows(const float* __restrict__ xm,
                                                  float* __restrict__ xs,
                                                  __nv_bfloat16* __restrict__ xsh,
                                                  __nv_bfloat16* __restrict__ xsl,
                                                  int* __restrict__ p) {
    const int n = NN;
    __shared__ unsigned long long keys[NN];
    __shared__ float vals[NN];
    __shared__ int   inv[NN];
    size_t row = (size_t)blockIdx.x * n;
    int tid = threadIdx.x;

    for (int i = tid; i < n; i += 1024) {
        float v = xm[row + i];
        vals[i] = v;
        unsigned int u = __float_as_uint(v);
        u = (u & 0x80000000u) ? ~u : (u | 0x80000000u);
        keys[i] = ((unsigned long long)u << 32) | (unsigned int)i;
    }
    __syncthreads();
    for (int k = 2; k <= n; k <<= 1) {
        for (int j = k >> 1; j > 0; j >>= 1) {
            #pragma unroll 2
            for (int i = tid; i < n; i += 1024) {
                int ixj = i ^ j;
                if (ixj > i) {
                    bool up = ((i & k) == 0);
                    unsigned long long a = keys[i];
                    unsigned long long b = keys[ixj];
                    if ((a > b) == up) { keys[i] = b; keys[ixj] = a; }
                }
            }
            __syncthreads();
        }
    }
    for (int i = tid; i < n; i += 1024) {
        int pi = (int)(keys[i] & 0xffffffffull);
        p[row + i] = pi;
        inv[pi] = i;
    }
    __syncthreads();
    for (int i = tid; i < n; i += 1024) {
        float v = vals[inv[i]];
        xs[row + i] = v;
        __nv_bfloat16 h = __float2bfloat16(v);
        xsh[row + i] = h;
        xsl[row + i] = __float2bfloat16(v - __bfloat162float(h));
    }
}

// ---------------- per-row unsort: out[j] = ys[p[j]] --------------------------
__global__ void unsort_rows(const float* __restrict__ ys,
                            const int* __restrict__ p,
                            float* __restrict__ out) {
    const int n = NN;
    __shared__ float buf[NN];
    size_t row = (size_t)blockIdx.x * n;
    for (int i = threadIdx.x; i < n; i += blockDim.x) buf[i] = ys[row + i];
    __syncthreads();
    for (int i = threadIdx.x; i < n; i += blockDim.x)
        out[row + i] = buf[p[row + i]];
}

// ======================= mma.sync bf16x3 NT GEMM =============================
// C[m,n] = act( sum_k A[m,k]*B[n,k] + bias[n] (+skip) ),  A~Ah+Al, B~Bh+Bl.
// 128x128 CTA tile, BK=64, 4 planes (Ah,Al,Bh,Bl) of 16KB in smem per stage,
// 3-stage cp.async pipeline. 8 warps: 4(m) x 2(n); warp tile 32x64.
// Pass loop hoisted OUTSIDE the (mt,np,sub) tile loops so consecutive HMMAs
// hit 16 distinct fp32 accumulators (kills the acc-RAW stall chain).
#define NSTAGES 3
#define GEMM_DYN_SMEM (NSTAGES * 65536 + 1024)

template<int RELU, int SKIP, int SPLITOUT>
__global__ __launch_bounds__(256, 1)
void gemm_mma(const __nv_bfloat16* __restrict__ Ah, const __nv_bfloat16* __restrict__ Al,
              const __nv_bfloat16* __restrict__ Bh, const __nv_bfloat16* __restrict__ Bl,
              const float* __restrict__ bias, const float* __restrict__ skip,
              float* __restrict__ Cf,
              __nv_bfloat16* __restrict__ Ch, __nv_bfloat16* __restrict__ Cl,
              int M, int Nn, int K) {
    extern __shared__ char dynsmem[];
    uint32_t tile0 = (smem_u32(dynsmem) + 1023u) & ~1023u;

    const int tid = threadIdx.x;
    const int wid = tid >> 5, lane = tid & 31;
    const int wm = wid & 3, wn = wid >> 2;        // 4 x 2 warp grid
    const int lm = lane & 15;
    const uint32_t hi16 = (uint32_t)(lane >> 4) << 4;
    const int bm = blockIdx.y * 128, bn = blockIdx.x * 128;

    // ---- loader mapping: 4096 16B chunks/stage, 16 per thread ----
    const __nv_bfloat16* srcs[16];
    uint32_t dsts[16];
    #pragma unroll
    for (int i = 0; i < 16; i++) {
        int c = tid + i * 256;
        int plane = c >> 10;            // 0:Ah 1:Al 2:Bh 3:Bl
        int r  = (c >> 3) & 127;
        int cc = c & 7;
        const __nv_bfloat16* bp = (plane == 0) ? Ah : (plane == 1) ? Al
                                 : (plane == 2) ? Bh : Bl;
        int row = ((plane < 2) ? bm : bn) + r;
        srcs[i] = bp + (size_t)row * K + cc * 8;
        dsts[i] = (uint32_t)plane * 16384u + swz128((uint32_t)(r * 128 + cc * 16));
    }

    float acc[2][8][4];
    #pragma unroll
    for (int a = 0; a < 2; a++)
        #pragma unroll
        for (int b = 0; b < 8; b++)
            #pragma unroll
            for (int c = 0; c < 4; c++) acc[a][b][c] = 0.0f;

    const int nk = K >> 6;

    // prologue: fill stages 0..NSTAGES-2
    #pragma unroll
    for (int s = 0; s < NSTAGES - 1; s++) {
        uint32_t sb = tile0 + (uint32_t)s * 65536u;
        #pragma unroll
        for (int i = 0; i < 16; i++)
            cp_async16(sb + dsts[i], srcs[i] + (size_t)s * 64);
        cp_commit();
    }

    // per-thread fragment row offsets (within-tile, swizzled row term)
    uint32_t aRow[2], bRow[4];
    #pragma unroll
    for (int mt = 0; mt < 2; mt++) {
        int r = wm * 32 + mt * 16 + lm;
        aRow[mt] = (uint32_t)r * 128u | ((uint32_t)(r & 7) << 20);
    }
    #pragma unroll
    for (int np = 0; np < 4; np++) {
        int r = wn * 64 + np * 16 + lm;
        bRow[np] = (uint32_t)r * 128u | ((uint32_t)(r & 7) << 20);
    }

    for (int kt = 0; kt < nk; ++kt) {
        // issue stage kt+NSTAGES-1
        if (kt + NSTAGES - 1 < nk) {
            uint32_t sb = tile0 + (uint32_t)((kt + NSTAGES - 1) % NSTAGES) * 65536u;
            #pragma unroll
            for (int i = 0; i < 16; i++)
                cp_async16(sb + dsts[i], srcs[i] + (size_t)(kt + NSTAGES - 1) * 64);
        }
        cp_commit();
        cp_wait2();              // stage kt resident
        __syncthreads();

        const uint32_t sb = tile0 + (uint32_t)(kt % NSTAGES) * 65536u;
        #pragma unroll
        for (int kb = 0; kb < 4; kb++) {
            const uint32_t cbase = (uint32_t)kb * 32u + hi16;
            uint32_t af[2][2][4];     // [plane][mt][4]
            #pragma unroll
            for (int mt = 0; mt < 2; mt++) {
                uint32_t xr = (aRow[mt] >> 20) << 4;
                uint32_t off = (aRow[mt] & 0xFFFFFu) + (cbase ^ xr);
                ldsm_x4(af[0][mt], sb + off);             // Ah
                ldsm_x4(af[1][mt], sb + 16384u + off);    // Al
            }
            uint32_t bf[2][4][4];     // [plane][np][4]
            #pragma unroll
            for (int np = 0; np < 4; np++) {
                uint32_t xr = (bRow[np] >> 20) << 4;
                uint32_t off = (bRow[np] & 0xFFFFFu) + (cbase ^ xr);
                ldsm_x4(bf[0][np], sb + 32768u + off);    // Bh
                ldsm_x4(bf[1][np], sb + 49152u + off);    // Bl
            }
            // pass loop OUTSIDE tile loops: 16 independent accumulators between
            // reuses of any acc -> no HMMA RAW stalls.
            #pragma unroll
            for (int pass = 0; pass < 3; pass++) {
                const int ap = (pass == 2) ? 1 : 0;   // Al only on pass 2
                const int bp = (pass == 1) ? 1 : 0;   // Bl only on pass 1
                #pragma unroll
                for (int mt = 0; mt < 2; mt++)
                    #pragma unroll
                    for (int np = 0; np < 4; np++)
                        #pragma unroll
                        for (int sub = 0; sub < 2; sub++)
                            mma_bf16(acc[mt][np * 2 + sub], af[ap][mt],
                                     bf[bp][np][sub], bf[bp][np][sub + 2]);
            }
        }
        __syncthreads();
    }

    // ---------------- epilogue ----------------
    const int lr = lane >> 2;          // 0..7
    const int lc = (lane & 3) * 2;     // 0,2,4,6
    #pragma unroll
    for (int nt = 0; nt < 8; nt++) {
        int c = bn + wn * 64 + nt * 8 + lc;
        float b0 = bias[c], b1 = bias[c + 1];
        #pragma unroll
        for (int mt = 0; mt < 2; mt++) {
            #pragma unroll
            for (int half = 0; half < 2; half++) {
                int r = bm + wm * 32 + mt * 16 + lr + half * 8;
                float v0 = acc[mt][nt][half * 2 + 0] + b0;
                float v1 = acc[mt][nt][half * 2 + 1] + b1;
                size_t off = (size_t)r * Nn + c;
                if (SKIP) {
                    float2 sv = *(const float2*)(skip + off);
                    v0 += sv.x; v1 += sv.y;
                }
                if (RELU) { v0 = fmaxf(v0, 0.0f); v1 = fmaxf(v1, 0.0f); }
                if (SPLITOUT) {
                    __nv_bfloat16 h0 = __float2bfloat16(v0);
                    __nv_bfloat16 h1 = __float2bfloat16(v1);
                    __nv_bfloat16 l0 = __float2bfloat16(v0 - __bfloat162float(h0));
                    __nv_bfloat16 l1 = __float2bfloat16(v1 - __bfloat162float(h1));
                    *(__nv_bfloat162*)(Ch + off) = __nv_bfloat162(h0, h1);
                    *(__nv_bfloat162*)(Cl + off) = __nv_bfloat162(l0, l1);
                } else {
                    *(float2*)(Cf + off) = make_float2(v0, v1);
                }
            }
        }
    }
}

// ---------------- launch ------------------------------------------------------
extern "C" void kernel_launch(void* const* d_in, const int* in_sizes, int n_in,
                              void* d_out, int out_size) {
    const float* x   = (const float*)d_in[0];
    const float* sw1 = (const float*)d_in[1];
    const float* sb1 = (const float*)d_in[2];
    const float* sw2 = (const float*)d_in[3];
    const float* sb2 = (const float*)d_in[4];
    const float* fw1 = (const float*)d_in[5];
    const float* fb1 = (const float*)d_in[6];
    const float* fw2 = (const float*)d_in[7];
    const float* fb2 = (const float*)d_in[8];
    float* out = (float*)d_out;

    void *pf1, *pf2, *pp, *pxh, *pxl, *phh, *phl;
    void *pw1h, *pw1l, *pw2h, *pw2l, *pw3h, *pw3l, *pw4h, *pw4l;
    cudaGetSymbolAddress(&pf1, g_f1);  cudaGetSymbolAddress(&pf2, g_f2);
    cudaGetSymbolAddress(&pp,  g_p);
    cudaGetSymbolAddress(&pxh, g_xh);  cudaGetSymbolAddress(&pxl, g_xl);
    cudaGetSymbolAddress(&phh, g_hh);  cudaGetSymbolAddress(&phl, g_hl);
    cudaGetSymbolAddress(&pw1h, g_w1h); cudaGetSymbolAddress(&pw1l, g_w1l);
    cudaGetSymbolAddress(&pw2h, g_w2h); cudaGetSymbolAddress(&pw2l, g_w2l);
    cudaGetSymbolAddress(&pw3h, g_w3h); cudaGetSymbolAddress(&pw3l, g_w3l);
    cudaGetSymbolAddress(&pw4h, g_w4h); cudaGetSymbolAddress(&pw4l, g_w4l);
    float* f1 = (float*)pf1;  float* f2 = (float*)pf2;  int* pidx = (int*)pp;
    __nv_bfloat16* xh = (__nv_bfloat16*)pxh; __nv_bfloat16* xl = (__nv_bfloat16*)pxl;
    __nv_bfloat16* hh = (__nv_bfloat16*)phh; __nv_bfloat16* hl = (__nv_bfloat16*)phl;
    __nv_bfloat16* w1h = (__nv_bfloat16*)pw1h; __nv_bfloat16* w1l = (__nv_bfloat16*)pw1l;
    __nv_bfloat16* w2h = (__nv_bfloat16*)pw2h; __nv_bfloat16* w2l = (__nv_bfloat16*)pw2l;
    __nv_bfloat16* w3h = (__nv_bfloat16*)pw3h; __nv_bfloat16* w3l = (__nv_bfloat16*)pw3l;
    __nv_bfloat16* w4h = (__nv_bfloat16*)pw4h; __nv_bfloat16* w4l = (__nv_bfloat16*)pw4l;

    cudaFuncSetAttribute(gemm_mma<1, 0, 1>, cudaFuncAttributeMaxDynamicSharedMemorySize, GEMM_DYN_SMEM);
    cudaFuncSetAttribute(gemm_mma<0, 1, 0>, cudaFuncAttributeMaxDynamicSharedMemorySize, GEMM_DYN_SMEM);
    cudaFuncSetAttribute(gemm_mma<0, 0, 0>, cudaFuncAttributeMaxDynamicSharedMemorySize, GEMM_DYN_SMEM);

    const int M1 = BB * FF;   // 32768
    const int M2 = BB * NN;   // 65536

    // weight hi/lo planes (recomputed every call; deterministic)
    split_plane<<<((size_t)HSZ * NN + 255) / 256, 256>>>(sw1, w1h, w1l, (size_t)HSZ * NN);
    split_plane<<<((size_t)NN * HSZ + 255) / 256, 256>>>(sw2, w2h, w2l, (size_t)NN * HSZ);
    split_plane<<<((size_t)HFZ * FF + 255) / 256, 256>>>(fw1, w3h, w3l, (size_t)HFZ * FF);
    split_plane<<<((size_t)OUTF * HFZ + 255) / 256, 256>>>(fw2, w4h, w4l, (size_t)OUTF * HFZ);

    // 1) xm = transpose(x): [B,N,F] -> [B,F,N]  -> f1
    transpose_batched<<<dim3(FF / 32, NN / 32, BB), dim3(32, 8)>>>(x, f1, NN, FF);

    // 2) stable argsort rows: xs fp32 -> f2, planes -> xh/xl, p -> pidx
    sort_rows<<<M1, 1024>>>(f1, f2, xh, xl, pidx);

    // 3) h = relu(xs @ sw1^T + sb1): planes out -> hh/hl
    gemm_mma<1, 0, 1><<<dim3(HSZ / 128, M1 / 128), 256, GEMM_DYN_SMEM>>>(
        xh, xl, w1h, w1l, sb1, nullptr, nullptr, hh, hl, M1, HSZ, NN);

    // 4) y_s = h @ sw2^T + sb2 + xs: fp32 out -> f1
    gemm_mma<0, 1, 0><<<dim3(NN / 128, M1 / 128), 256, GEMM_DYN_SMEM>>>(
        hh, hl, w2h, w2l, sb2, f2, f1, nullptr, nullptr, M1, NN, HSZ);

    // 5) unsort -> f2
    unsort_rows<<<M1, 256>>>(f1, pidx, f2);

    // 6) transpose back [B,F,N]->[B,N,F] with split -> xh/xl
    transpose_split<<<dim3(NN / 32, FF / 32, BB), dim3(32, 8)>>>(f2, xh, xl, FF, NN);

    // 7) h2 = relu(y @ fw1^T + fb1): planes out -> hh/hl
    gemm_mma<1, 0, 1><<<dim3(HFZ / 128, M2 / 128), 256, GEMM_DYN_SMEM>>>(
        xh, xl, w3h, w3l, fb1, nullptr, nullptr, hh, hl, M2, HFZ, FF);

    // 8) out = h2 @ fw2^T + fb2: fp32 -> d_out
    gemm_mma<0, 0, 0><<<dim3(OUTF / 128, M2 / 128), 256, GEMM_DYN_SMEM>>>(
        hh, hl, w4h, w4l, fb2, nullptr, out, nullptr, nullptr, M2, OUTF, HFZ);

    (void)in_sizes; (void)n_in; (void)out_size;
}

// round 9
// speedup vs baseline: 2.5082x; 1.0195x over previous
#include <cuda_runtime.h>
#include <cuda_bf16.h>
#include <cstdint>

// Problem dims (fixed)
#define BB   32
#define NN   2048
#define FF   1024
#define HSZ  8192   // 4*N
#define HFZ  4096   // 4*F
#define OUTF 1024

// ---------------- scratch (device globals; no allocations allowed) ----------
__device__ float g_f1[(size_t)BB * FF * NN];            // 256 MB
__device__ float g_f2[(size_t)BB * FF * NN];            // 256 MB
__device__ int   g_p [(size_t)BB * FF * NN];            // 256 MB
__device__ __nv_bfloat16 g_xh[(size_t)BB * FF * NN];    // xs / y planes
__device__ __nv_bfloat16 g_xl[(size_t)BB * FF * NN];
__device__ __nv_bfloat16 g_hh[(size_t)BB * FF * HSZ];   // h / h2 planes
__device__ __nv_bfloat16 g_hl[(size_t)BB * FF * HSZ];
__device__ __nv_bfloat16 g_w1h[(size_t)HSZ * NN],  g_w1l[(size_t)HSZ * NN];
__device__ __nv_bfloat16 g_w2h[(size_t)NN * HSZ],  g_w2l[(size_t)NN * HSZ];
__device__ __nv_bfloat16 g_w3h[(size_t)HFZ * FF],  g_w3l[(size_t)HFZ * FF];
__device__ __nv_bfloat16 g_w4h[(size_t)OUTF * HFZ], g_w4l[(size_t)OUTF * HFZ];

// ======================= PTX helpers (compute_103-safe) ======================
__device__ __forceinline__ uint32_t smem_u32(const void* p) {
    uint32_t a;
    asm("{ .reg .u64 t; cvta.to.shared.u64 t, %1; cvt.u32.u64 %0, t; }"
        : "=r"(a) : "l"(p));
    return a;
}
__device__ __forceinline__ void cp_async16(uint32_t dst, const void* src) {
    asm volatile("cp.async.cg.shared.global [%0], [%1], 16;" :: "r"(dst), "l"(src));
}
__device__ __forceinline__ void cp_commit() {
    asm volatile("cp.async.commit_group;" ::: "memory");
}
template<int N>
__device__ __forceinline__ void cp_wait() {
    asm volatile("cp.async.wait_group %0;" :: "n"(N) : "memory");
}
__device__ __forceinline__ void ldsm_x4(uint32_t* r, uint32_t addr) {
    asm volatile("ldmatrix.sync.aligned.m8n8.x4.shared.b16 {%0,%1,%2,%3}, [%4];"
                 : "=r"(r[0]), "=r"(r[1]), "=r"(r[2]), "=r"(r[3]) : "r"(addr));
}
__device__ __forceinline__ void mma_bf16(float* d, const uint32_t* a,
                                         uint32_t b0, uint32_t b1) {
    asm volatile(
        "mma.sync.aligned.m16n8k16.row.col.f32.bf16.bf16.f32 "
        "{%0,%1,%2,%3}, {%4,%5,%6,%7}, {%8,%9}, {%0,%1,%2,%3};"
        : "+f"(d[0]), "+f"(d[1]), "+f"(d[2]), "+f"(d[3])
        : "r"(a[0]), "r"(a[1]), "r"(a[2]), "r"(a[3]), "r"(b0), "r"(b1));
}
__device__ __forceinline__ uint32_t swz128(uint32_t off) {
    return off ^ ((off >> 3) & 0x70u);
}

// ---------------- batched transpose: in [batch, R, C] -> out [batch, C, R] --
__global__ void transpose_batched(const float* __restrict__ in,
                                  float* __restrict__ out, int R, int C) {
    __shared__ float tile[32][33];
    int b  = blockIdx.z;
    int c0 = blockIdx.x * 32;
    int r0 = blockIdx.y * 32;
    const float* ib = in  + (size_t)b * R * C;
    float*       ob = out + (size_t)b * R * C;
    int x = threadIdx.x;
    #pragma unroll
    for (int i = threadIdx.y; i < 32; i += 8)
        tile[i][x] = ib[(size_t)(r0 + i) * C + (c0 + x)];
    __syncthreads();
    #pragma unroll
    for (int i = threadIdx.y; i < 32; i += 8)
        ob[(size_t)(c0 + i) * R + (r0 + x)] = tile[x][i];
}

// transpose + bf16 hi/lo split output
__global__ void transpose_split(const float* __restrict__ in,
                                __nv_bfloat16* __restrict__ oh,
                                __nv_bfloat16* __restrict__ ol, int R, int C) {
    __shared__ float tile[32][33];
    int b  = blockIdx.z;
    int c0 = blockIdx.x * 32;
    int r0 = blockIdx.y * 32;
    const float* ib = in + (size_t)b * R * C;
    size_t ob = (size_t)b * R * C;
    int x = threadIdx.x;
    #pragma unroll
    for (int i = threadIdx.y; i < 32; i += 8)
        tile[i][x] = ib[(size_t)(r0 + i) * C + (c0 + x)];
    __syncthreads();
    #pragma unroll
    for (int i = threadIdx.y; i < 32; i += 8) {
        float v = tile[x][i];
        __nv_bfloat16 h = __float2bfloat16(v);
        size_t idx = ob + (size_t)(c0 + i) * R + (r0 + x);
        oh[idx] = h;
        ol[idx] = __float2bfloat16(v - __bfloat162float(h));
    }
}

// weight split: hi = bf16(w), lo = bf16(w - hi)
__global__ void split_plane(const float* __restrict__ w,
                            __nv_bfloat16* __restrict__ hi,
                            __nv_bfloat16* __restrict__ lo, size_t n) {
    size_t i = (size_t)blockIdx.x * blockDim.x + threadIdx.x;
    if (i < n) {
        float v = w[i];
        __nv_bfloat16 h = __float2bfloat16(v);
        hi[i] = h;
        lo[i] = __float2bfloat16(v - __bfloat162float(h));
    }
}

// ---------------- per-row stable argsort (bitonic on 64-bit keys) -----------
__global__ __launch_bounds__(1024) void sort_rows(const float* __restrict__ xm,
                                                  float* __restrict__ xs,
                                                  __nv_bfloat16* __restrict__ xsh,
                                                  __nv_bfloat16* __restrict__ xsl,
                                                  int* __restrict__ p) {
    const int n = NN;
    __shared__ unsigned long long keys[NN];
    __shared__ float vals[NN];
    __shared__ int   inv[NN];
    size_t row = (size_t)blockIdx.x * n;
    int tid = threadIdx.x;

    for (int i = tid; i < n; i += 1024) {
        float v = xm[row + i];
        vals[i] = v;
        unsigned int u = __float_as_uint(v);
        u = (u & 0x80000000u) ? ~u : (u | 0x80000000u);
        keys[i] = ((unsigned long long)u << 32) | (unsigned int)i;
    }
    __syncthreads();
    for (int k = 2; k <= n; k <<= 1) {
        for (int j = k >> 1; j > 0; j >>= 1) {
            #pragma unroll 2
            for (int i = tid; i < n; i += 1024) {
                int ixj = i ^ j;
                if (ixj > i) {
                    bool up = ((i & k) == 0);
                    unsigned long long a = keys[i];
                    unsigned long long b = keys[ixj];
                    if ((a > b) == up) { keys[i] = b; keys[ixj] = a; }
                }
            }
            __syncthreads();
        }
    }
    for (int i = tid; i < n; i += 1024) {
        int pi = (int)(keys[i] & 0xffffffffull);
        p[row + i] = pi;
        inv[pi] = i;
    }
    __syncthreads();
    for (int i = tid; i < n; i += 1024) {
        float v = vals[inv[i]];
        xs[row + i] = v;
        __nv_bfloat16 h = __float2bfloat16(v);
        xsh[row + i] = h;
        xsl[row + i] = __float2bfloat16(v - __bfloat162float(h));
    }
}

// ---------------- per-row unsort: out[j] = ys[p[j]] --------------------------
__global__ void unsort_rows(const float* __restrict__ ys,
                            const int* __restrict__ p,
                            float* __restrict__ out) {
    const int n = NN;
    __shared__ float buf[NN];
    size_t row = (size_t)blockIdx.x * n;
    for (int i = threadIdx.x; i < n; i += blockDim.x) buf[i] = ys[row + i];
    __syncthreads();
    for (int i = threadIdx.x; i < n; i += blockDim.x)
        out[row + i] = buf[p[row + i]];
}

// ======================= mma.sync bf16x3 NT GEMM (v2) ========================
// BM=256, BN=128, BK=64. 8 warps: 4(m) x 2(n); warp tile 64x64.
// 2-stage cp.async pipeline, stage = Ah(32K)+Al(32K)+Bh(16K)+Bl(16K) = 96KB.
// 3 split passes hoisted outside tile loops (32 independent accumulators).
#define STAGE_BYTES 98304
#define GEMM_DYN_SMEM (2 * STAGE_BYTES + 1024)

template<int RELU, int SKIP, int SPLITOUT>
__global__ __launch_bounds__(256, 1)
void gemm_mma(const __nv_bfloat16* __restrict__ Ah, const __nv_bfloat16* __restrict__ Al,
              const __nv_bfloat16* __restrict__ Bh, const __nv_bfloat16* __restrict__ Bl,
              const float* __restrict__ bias, const float* __restrict__ skip,
              float* __restrict__ Cf,
              __nv_bfloat16* __restrict__ Ch, __nv_bfloat16* __restrict__ Cl,
              int M, int Nn, int K) {
    extern __shared__ char dynsmem[];
    uint32_t tile0 = (smem_u32(dynsmem) + 1023u) & ~1023u;

    const int tid = threadIdx.x;
    const int wid = tid >> 5, lane = tid & 31;
    const int wm = wid & 3, wn = wid >> 2;        // 4(m) x 2(n) warp grid
    const int lm = lane & 15;
    const uint32_t hi16 = (uint32_t)(lane >> 4) << 4;
    const int bm = blockIdx.y * 256, bn = blockIdx.x * 128;

    // ---- loader: rbase = tid>>3 (0..31), cc = tid&7; rows rbase + j*32 ----
    const int rbase = tid >> 3, cc = tid & 7;
    const __nv_bfloat16* pAh = Ah + (size_t)(bm + rbase) * K + cc * 8;
    const __nv_bfloat16* pAl = Al + (size_t)(bm + rbase) * K + cc * 8;
    const __nv_bfloat16* pBh = Bh + (size_t)(bn + rbase) * K + cc * 8;
    const __nv_bfloat16* pBl = Bl + (size_t)(bn + rbase) * K + cc * 8;
    const size_t rowStep = (size_t)32 * K;         // j stride (elements)
    const uint32_t dstA = (uint32_t)rbase * 128u +
                          ((uint32_t)cc * 16u ^ ((uint32_t)(rbase & 7) << 4));

    float acc[4][8][4];
    #pragma unroll
    for (int a = 0; a < 4; a++)
        #pragma unroll
        for (int b = 0; b < 8; b++)
            #pragma unroll
            for (int c = 0; c < 4; c++) acc[a][b][c] = 0.0f;

    const int nk = K >> 5;  // dummy; real below
    const int nkt = K >> 6;

    // prologue: stage 0 (k-offset 0)
    {
        uint32_t sb = tile0;
        #pragma unroll
        for (int j = 0; j < 8; j++) {
            cp_async16(sb + dstA + j * 4096u,          pAh + (size_t)j * rowStep);
            cp_async16(sb + 32768u + dstA + j * 4096u, pAl + (size_t)j * rowStep);
        }
        #pragma unroll
        for (int j = 0; j < 4; j++) {
            cp_async16(sb + 65536u + dstA + j * 4096u, pBh + (size_t)j * rowStep);
            cp_async16(sb + 81920u + dstA + j * 4096u, pBl + (size_t)j * rowStep);
        }
        cp_commit();
    }

    for (int kt = 0; kt < nkt; ++kt) {
        if (kt + 1 < nkt) {
            uint32_t sb = tile0 + (uint32_t)((kt + 1) & 1) * STAGE_BYTES;
            size_t ko = (size_t)(kt + 1) * 64;
            #pragma unroll
            for (int j = 0; j < 8; j++) {
                cp_async16(sb + dstA + j * 4096u,          pAh + ko + (size_t)j * rowStep);
                cp_async16(sb + 32768u + dstA + j * 4096u, pAl + ko + (size_t)j * rowStep);
            }
            #pragma unroll
            for (int j = 0; j < 4; j++) {
                cp_async16(sb + 65536u + dstA + j * 4096u, pBh + ko + (size_t)j * rowStep);
                cp_async16(sb + 81920u + dstA + j * 4096u, pBl + ko + (size_t)j * rowStep);
            }
            cp_commit();
            cp_wait<1>();
        } else {
            cp_wait<0>();
        }
        __syncthreads();

        const uint32_t sb = tile0 + (uint32_t)(kt & 1) * STAGE_BYTES;
        #pragma unroll
        for (int kb = 0; kb < 4; kb++) {
            const uint32_t cbase = (uint32_t)kb * 32u + hi16;
            uint32_t af[2][4][4];
            #pragma unroll
            for (int mt = 0; mt < 4; mt++) {
                int r = wm * 64 + mt * 16 + lm;
                uint32_t off = (uint32_t)r * 128u + (cbase ^ ((uint32_t)(r & 7) << 4));
                ldsm_x4(af[0][mt], sb + off);             // Ah
                ldsm_x4(af[1][mt], sb + 32768u + off);    // Al
            }
            uint32_t bf[2][4][4];
            #pragma unroll
            for (int np = 0; np < 4; np++) {
                int r = wn * 64 + np * 16 + lm;
                uint32_t off = (uint32_t)r * 128u + (cbase ^ ((uint32_t)(r & 7) << 4));
                ldsm_x4(bf[0][np], sb + 65536u + off);    // Bh
                ldsm_x4(bf[1][np], sb + 81920u + off);    // Bl
            }
            #pragma unroll
            for (int pass = 0; pass < 3; pass++) {
                const int ap = (pass == 2) ? 1 : 0;
                const int bp = (pass == 1) ? 1 : 0;
                #pragma unroll
                for (int mt = 0; mt < 4; mt++)
                    #pragma unroll
                    for (int np = 0; np < 4; np++)
                        #pragma unroll
                        for (int sub = 0; sub < 2; sub++)
                            mma_bf16(acc[mt][np * 2 + sub], af[ap][mt],
                                     bf[bp][np][sub], bf[bp][np][sub + 2]);
            }
        }
        __syncthreads();
    }
    (void)nk;

    // ---------------- epilogue ----------------
    const int lr = lane >> 2;          // 0..7
    const int lc = (lane & 3) * 2;     // 0,2,4,6
    #pragma unroll
    for (int nt = 0; nt < 8; nt++) {
        int c = bn + wn * 64 + nt * 8 + lc;
        float b0 = bias[c], b1 = bias[c + 1];
        #pragma unroll
        for (int mt = 0; mt < 4; mt++) {
            #pragma unroll
            for (int half = 0; half < 2; half++) {
                int r = bm + wm * 64 + mt * 16 + lr + half * 8;
                float v0 = acc[mt][nt][half * 2 + 0] + b0;
                float v1 = acc[mt][nt][half * 2 + 1] + b1;
                size_t off = (size_t)r * Nn + c;
                if (SKIP) {
                    float2 sv = *(const float2*)(skip + off);
                    v0 += sv.x; v1 += sv.y;
                }
                if (RELU) { v0 = fmaxf(v0, 0.0f); v1 = fmaxf(v1, 0.0f); }
                if (SPLITOUT) {
                    __nv_bfloat16 h0 = __float2bfloat16(v0);
                    __nv_bfloat16 h1 = __float2bfloat16(v1);
                    __nv_bfloat16 l0 = __float2bfloat16(v0 - __bfloat162float(h0));
                    __nv_bfloat16 l1 = __float2bfloat16(v1 - __bfloat162float(h1));
                    *(__nv_bfloat162*)(Ch + off) = __nv_bfloat162(h0, h1);
                    *(__nv_bfloat162*)(Cl + off) = __nv_bfloat162(l0, l1);
                } else {
                    *(float2*)(Cf + off) = make_float2(v0, v1);
                }
            }
        }
    }
}

// ---------------- launch ------------------------------------------------------
extern "C" void kernel_launch(void* const* d_in, const int* in_sizes, int n_in,
                              void* d_out, int out_size) {
    const float* x   = (const float*)d_in[0];
    const float* sw1 = (const float*)d_in[1];
    const float* sb1 = (const float*)d_in[2];
    const float* sw2 = (const float*)d_in[3];
    const float* sb2 = (const float*)d_in[4];
    const float* fw1 = (const float*)d_in[5];
    const float* fb1 = (const float*)d_in[6];
    const float* fw2 = (const float*)d_in[7];
    const float* fb2 = (const float*)d_in[8];
    float* out = (float*)d_out;

    void *pf1, *pf2, *pp, *pxh, *pxl, *phh, *phl;
    void *pw1h, *pw1l, *pw2h, *pw2l, *pw3h, *pw3l, *pw4h, *pw4l;
    cudaGetSymbolAddress(&pf1, g_f1);  cudaGetSymbolAddress(&pf2, g_f2);
    cudaGetSymbolAddress(&pp,  g_p);
    cudaGetSymbolAddress(&pxh, g_xh);  cudaGetSymbolAddress(&pxl, g_xl);
    cudaGetSymbolAddress(&phh, g_hh);  cudaGetSymbolAddress(&phl, g_hl);
    cudaGetSymbolAddress(&pw1h, g_w1h); cudaGetSymbolAddress(&pw1l, g_w1l);
    cudaGetSymbolAddress(&pw2h, g_w2h); cudaGetSymbolAddress(&pw2l, g_w2l);
    cudaGetSymbolAddress(&pw3h, g_w3h); cudaGetSymbolAddress(&pw3l, g_w3l);
    cudaGetSymbolAddress(&pw4h, g_w4h); cudaGetSymbolAddress(&pw4l, g_w4l);
    float* f1 = (float*)pf1;  float* f2 = (float*)pf2;  int* pidx = (int*)pp;
    __nv_bfloat16* xh = (__nv_bfloat16*)pxh; __nv_bfloat16* xl = (__nv_bfloat16*)pxl;
    __nv_bfloat16* hh = (__nv_bfloat16*)phh; __nv_bfloat16* hl = (__nv_bfloat16*)phl;
    __nv_bfloat16* w1h = (__nv_bfloat16*)pw1h; __nv_bfloat16* w1l = (__nv_bfloat16*)pw1l;
    __nv_bfloat16* w2h = (__nv_bfloat16*)pw2h; __nv_bfloat16* w2l = (__nv_bfloat16*)pw2l;
    __nv_bfloat16* w3h = (__nv_bfloat16*)pw3h; __nv_bfloat16* w3l = (__nv_bfloat16*)pw3l;
    __nv_bfloat16* w4h = (__nv_bfloat16*)pw4h; __nv_bfloat16* w4l = (__nv_bfloat16*)pw4l;

    cudaFuncSetAttribute(gemm_mma<1, 0, 1>, cudaFuncAttributeMaxDynamicSharedMemorySize, GEMM_DYN_SMEM);
    cudaFuncSetAttribute(gemm_mma<0, 1, 0>, cudaFuncAttributeMaxDynamicSharedMemorySize, GEMM_DYN_SMEM);
    cudaFuncSetAttribute(gemm_mma<0, 0, 0>, cudaFuncAttributeMaxDynamicSharedMemorySize, GEMM_DYN_SMEM);

    const int M1 = BB * FF;   // 32768
    const int M2 = BB * NN;   // 65536

    // Launch order puts gemm1 at position 6 so ncu (-s 5 -c 1) profiles it.
    // 1) xm = transpose(x)
    transpose_batched<<<dim3(FF / 32, NN / 32, BB), dim3(32, 8)>>>(x, f1, NN, FF);
    // 2) stable argsort rows
    sort_rows<<<M1, 1024>>>(f1, f2, xh, xl, pidx);
    // 3-5) weight splits needed by gemms 1-3
    split_plane<<<((size_t)HSZ * NN + 255) / 256, 256>>>(sw1, w1h, w1l, (size_t)HSZ * NN);
    split_plane<<<((size_t)NN * HSZ + 255) / 256, 256>>>(sw2, w2h, w2l, (size_t)NN * HSZ);
    split_plane<<<((size_t)HFZ * FF + 255) / 256, 256>>>(fw1, w3h, w3l, (size_t)HFZ * FF);

    // 6) h = relu(xs @ sw1^T + sb1)  [PROFILED]
    gemm_mma<1, 0, 1><<<dim3(HSZ / 128, M1 / 256), 256, GEMM_DYN_SMEM>>>(
        xh, xl, w1h, w1l, sb1, nullptr, nullptr, hh, hl, M1, HSZ, NN);

    // 7) y_s = h @ sw2^T + sb2 + xs
    gemm_mma<0, 1, 0><<<dim3(NN / 128, M1 / 256), 256, GEMM_DYN_SMEM>>>(
        hh, hl, w2h, w2l, sb2, f2, f1, nullptr, nullptr, M1, NN, HSZ);

    // 8) unsort
    unsort_rows<<<M1, 256>>>(f1, pidx, f2);
    // 9) transpose back with split
    transpose_split<<<dim3(NN / 32, FF / 32, BB), dim3(32, 8)>>>(f2, xh, xl, FF, NN);
    // 10) split w4
    split_plane<<<((size_t)OUTF * HFZ + 255) / 256, 256>>>(fw2, w4h, w4l, (size_t)OUTF * HFZ);

    // 11) h2 = relu(y @ fw1^T + fb1)
    gemm_mma<1, 0, 1><<<dim3(HFZ / 128, M2 / 256), 256, GEMM_DYN_SMEM>>>(
        xh, xl, w3h, w3l, fb1, nullptr, nullptr, hh, hl, M2, HFZ, FF);

    // 12) out = h2 @ fw2^T + fb2
    gemm_mma<0, 0, 0><<<dim3(OUTF / 128, M2 / 256), 256, GEMM_DYN_SMEM>>>(
        hh, hl, w4h, w4l, fb2, nullptr, out, nullptr, nullptr, M2, OUTF, HFZ);

    (void)in_sizes; (void)n_in; (void)out_size;
}